// round 3
// baseline (speedup 1.0000x reference)
#include <cuda_runtime.h>
#include <math.h>
#include <stdint.h>

#define NTOK  4096
#define DIM   768
#define DEPTH 6
#define HEADS 12
#define DH    64
#define FFD   3072
#define MFEAT 256
#define NOUT  102

// ---------------- scratch (static device globals; no allocations) ----------
__device__ float g_x  [NTOK*DIM];
__device__ float g_h  [NTOK*DIM];
__device__ float g_q  [NTOK*DIM];
__device__ float g_k  [NTOK*DIM];
__device__ float g_v  [NTOK*DIM];
__device__ float g_o  [NTOK*DIM];
__device__ float g_ff [NTOK*FFD];
__device__ float g_qf [HEADS*NTOK*MFEAT];
__device__ float g_kf [HEADS*NTOK*MFEAT];
__device__ float g_diag[HEADS*NTOK];
__device__ unsigned g_hmax[HEADS];
__device__ float g_ksum[HEADS*MFEAT];
__device__ float g_ctx [HEADS*MFEAT*DH];
__device__ float g_dinv[HEADS*NTOK];
__device__ int   g_bidx[NTOK];

// ---------------- helpers ---------------------------------------------------
__device__ __forceinline__ unsigned f2o(float f) {
    unsigned u = __float_as_uint(f);
    return (u & 0x80000000u) ? ~u : (u | 0x80000000u);
}
__device__ __forceinline__ float o2f(unsigned u) {
    return __uint_as_float((u & 0x80000000u) ? (u & 0x7fffffffu) : ~u);
}
__device__ __forceinline__ float gelu_tanh(float x) {
    float x3 = x * x * x;
    return 0.5f * x * (1.0f + tanhf(0.7978845608028654f * (x + 0.044715f * x3)));
}

// ---------------- embedding -------------------------------------------------
// idx = searchsorted-left over boundaries[:-1] where
// boundaries = [-2, -1] ++ linspace(0,1,101); drop last (1.0).
__global__ void bucket_kernel(const float* __restrict__ methy, int* __restrict__ idx) {
    int n = blockIdx.x * 256 + threadIdx.x;
    if (n >= NTOK) return;
    float v = methy[n];
    int c = 0;
    c += (v > -2.0f);
    c += (v > -1.0f);
    #pragma unroll
    for (int k = 0; k < 100; k++) c += (v > (float)k * 0.01f);
    idx[n] = c;
}

__global__ void embed_kernel(const int* __restrict__ idx, const int* __restrict__ pos,
                             const int* __restrict__ chromo,
                             const float* __restrict__ mtab, const float* __restrict__ ptab,
                             const float* __restrict__ ctab, float* __restrict__ x) {
    int n = blockIdx.x;
    int t = threadIdx.x;
    int mi = idx[n], pi = pos[n], ci = chromo[n];
    #pragma unroll
    for (int i = 0; i < 3; i++) {
        int d = t + i * 256;
        x[(size_t)n * DIM + d] = mtab[(size_t)mi * DIM + d]
                               + ptab[(size_t)pi * DIM + d]
                               + ctab[(size_t)ci * DIM + d];
    }
}

// ---------------- layernorm (one block per row, 768 = 3*256) ----------------
__global__ void ln_kernel(const float* __restrict__ x, const float* __restrict__ g,
                          const float* __restrict__ b, float* __restrict__ out) {
    __shared__ float red[256];
    int n = blockIdx.x, t = threadIdx.x;
    const float* xr = x + (size_t)n * DIM;
    float v0 = xr[t], v1 = xr[t + 256], v2 = xr[t + 512];
    red[t] = v0 + v1 + v2;
    __syncthreads();
    for (int s = 128; s; s >>= 1) { if (t < s) red[t] += red[t + s]; __syncthreads(); }
    float mu = red[0] * (1.0f / 768.0f);
    __syncthreads();
    float d0 = v0 - mu, d1 = v1 - mu, d2 = v2 - mu;
    red[t] = d0 * d0 + d1 * d1 + d2 * d2;
    __syncthreads();
    for (int s = 128; s; s >>= 1) { if (t < s) red[t] += red[t + s]; __syncthreads(); }
    float rstd = rsqrtf(red[0] * (1.0f / 768.0f) + 1e-5f);
    float* o = out + (size_t)n * DIM;
    o[t]       = d0 * rstd * g[t]       + b[t];
    o[t + 256] = d1 * rstd * g[t + 256] + b[t + 256];
    o[t + 512] = d2 * rstd * g[t + 512] + b[t + 512];
}

// ---------------- generic tiled SGEMM (128x128x8, 8x8 micro-tile) -----------
// EPI: 0 = none, 1 = +bias, 2 = gelu(+bias), 3 = +bias +res
template<int EPI>
__global__ __launch_bounds__(256)
void sgemm_kernel(const float* __restrict__ A, const float* __restrict__ B,
                  const float* __restrict__ bias, const float* __restrict__ res,
                  float* __restrict__ C, int M, int N, int K) {
    __shared__ float As[8][128];
    __shared__ float Bs[8][128];
    int tid = threadIdx.x;
    int row0 = blockIdx.y * 128, col0 = blockIdx.x * 128;
    int tx = tid & 15, ty = tid >> 4;
    int arow = tid >> 1, acol = (tid & 1) * 4;
    int brow = tid >> 5, bcol = (tid & 31) * 4;
    bool baln = ((N & 3) == 0) && (col0 + 128 <= N);
    float acc[8][8];
    #pragma unroll
    for (int i = 0; i < 8; i++)
        #pragma unroll
        for (int j = 0; j < 8; j++) acc[i][j] = 0.0f;

    for (int k0 = 0; k0 < K; k0 += 8) {
        float4 av = *(const float4*)(A + (size_t)(row0 + arow) * K + k0 + acol);
        As[acol + 0][arow] = av.x; As[acol + 1][arow] = av.y;
        As[acol + 2][arow] = av.z; As[acol + 3][arow] = av.w;
        if (baln) {
            float4 bv = *(const float4*)(B + (size_t)(k0 + brow) * N + col0 + bcol);
            Bs[brow][bcol + 0] = bv.x; Bs[brow][bcol + 1] = bv.y;
            Bs[brow][bcol + 2] = bv.z; Bs[brow][bcol + 3] = bv.w;
        } else {
            #pragma unroll
            for (int j = 0; j < 4; j++) {
                int c = col0 + bcol + j;
                Bs[brow][bcol + j] = (c < N) ? B[(size_t)(k0 + brow) * N + c] : 0.0f;
            }
        }
        __syncthreads();
        #pragma unroll
        for (int kk = 0; kk < 8; kk++) {
            float a[8], bb[8];
            #pragma unroll
            for (int i = 0; i < 8; i++) a[i] = As[kk][ty + 16 * i];
            #pragma unroll
            for (int j = 0; j < 8; j++) bb[j] = Bs[kk][tx + 16 * j];
            #pragma unroll
            for (int i = 0; i < 8; i++)
                #pragma unroll
                for (int j = 0; j < 8; j++) acc[i][j] += a[i] * bb[j];
        }
        __syncthreads();
    }
    #pragma unroll
    for (int i = 0; i < 8; i++) {
        int r = row0 + ty + 16 * i;
        #pragma unroll
        for (int j = 0; j < 8; j++) {
            int c = col0 + tx + 16 * j;
            if (c < N) {
                float v = acc[i][j];
                if (EPI >= 1) v += bias[c];
                if (EPI == 2) v = gelu_tanh(v);
                if (EPI == 3) v += res[(size_t)r * N + c];
                C[(size_t)r * N + c] = v;
            }
        }
    }
}

// ---------------- FAVOR+ kernels --------------------------------------------
// queries: per-(h,n) block: xd = (q*dnorm)@proj^T, row max, exp -> qf
__global__ void favor_q_kernel(const float* __restrict__ q, const float* __restrict__ proj,
                               float* __restrict__ qf) {
    int n = blockIdx.x, h = blockIdx.y, t = threadIdx.x;
    __shared__ float sq[64];
    __shared__ float red[256];
    if (t < 64) sq[t] = q[(size_t)n * DIM + h * DH + t] * 0.35355339059327373f;
    __syncthreads();
    float diag = 0.0f;
    #pragma unroll
    for (int d = 0; d < 64; d++) diag += sq[d] * sq[d];
    diag *= 0.5f;
    const float* pr = proj + (size_t)t * DH;
    float xd = 0.0f;
    #pragma unroll
    for (int d = 0; d < 64; d++) xd += sq[d] * pr[d];
    red[t] = xd;
    __syncthreads();
    for (int s = 128; s; s >>= 1) { if (t < s) red[t] = fmaxf(red[t], red[t + s]); __syncthreads(); }
    float mx = red[0];
    qf[((size_t)((h << 12) + n)) * MFEAT + t] = 0.0625f * (expf(xd - diag - mx) + 1e-4f);
}

// keys pass1: xd -> kf (raw), diag, per-head global max (ordered-uint atomicMax)
__global__ void favor_k1_kernel(const float* __restrict__ k, const float* __restrict__ proj,
                                float* __restrict__ kf, float* __restrict__ diagb,
                                unsigned* __restrict__ hmax) {
    int n = blockIdx.x, h = blockIdx.y, t = threadIdx.x;
    __shared__ float sq[64];
    __shared__ float red[256];
    if (t < 64) sq[t] = k[(size_t)n * DIM + h * DH + t] * 0.35355339059327373f;
    __syncthreads();
    float diag = 0.0f;
    #pragma unroll
    for (int d = 0; d < 64; d++) diag += sq[d] * sq[d];
    diag *= 0.5f;
    const float* pr = proj + (size_t)t * DH;
    float xd = 0.0f;
    #pragma unroll
    for (int d = 0; d < 64; d++) xd += sq[d] * pr[d];
    kf[((size_t)((h << 12) + n)) * MFEAT + t] = xd;
    red[t] = xd;
    __syncthreads();
    for (int s = 128; s; s >>= 1) { if (t < s) red[t] = fmaxf(red[t], red[t + s]); __syncthreads(); }
    if (t == 0) {
        atomicMax(hmax + h, f2o(red[0]));
        diagb[(h << 12) + n] = diag;
    }
}

// keys pass2: kf = ratio*(exp(xd - diag - mx) + eps) * mask[n]
__global__ void favor_k2_kernel(float* __restrict__ kf, const float* __restrict__ diagb,
                                const unsigned* __restrict__ hmax,
                                const float* __restrict__ methy) {
    size_t i = (size_t)blockIdx.x * 256 + threadIdx.x;   // HEADS*NTOK*MFEAT elems
    size_t hn = i >> 8;
    int n = (int)(hn & 4095);
    int h = (int)(hn >> 12);
    float mx = o2f(hmax[h]);
    float v = 0.0625f * (expf(kf[i] - diagb[hn] - mx) + 1e-4f);
    kf[i] = (methy[n] != 0.0f) ? v : 0.0f;
}

// k_sum[h,m] += sum over 256-row n-chunk
__global__ void ksum_kernel(const float* __restrict__ kf, float* __restrict__ ksum) {
    int h = blockIdx.y, m = threadIdx.x;
    int n0 = blockIdx.x * 256;
    float s = 0.0f;
    for (int n = n0; n < n0 + 256; n++)
        s += kf[((size_t)((h << 12) + n)) * MFEAT + m];
    atomicAdd(&ksum[h * MFEAT + m], s);
}

// ctx[h,m,d] += sum_n kf[h,n,m]*v[n,h,d]   (split over n, atomic accumulate)
__global__ void ctx_kernel(const float* __restrict__ kf, const float* __restrict__ v,
                           float* __restrict__ ctx) {
    int h = blockIdx.y;
    int n0 = blockIdx.x * 128;
    int t = threadIdx.x;
    __shared__ float sv[4][64];
    float acc[64];
    #pragma unroll
    for (int d = 0; d < 64; d++) acc[d] = 0.0f;
    int rr = t >> 6, cc = t & 63;
    for (int n = n0; n < n0 + 128; n += 4) {
        sv[rr][cc] = v[(size_t)(n + rr) * DIM + h * DH + cc];
        __syncthreads();
        #pragma unroll
        for (int r = 0; r < 4; r++) {
            float kv = kf[((size_t)((h << 12) + n + r)) * MFEAT + t];
            #pragma unroll
            for (int d = 0; d < 64; d++) acc[d] += kv * sv[r][d];
        }
        __syncthreads();
    }
    float* cp = ctx + ((size_t)h * MFEAT + t) * DH;
    #pragma unroll
    for (int d = 0; d < 64; d++) atomicAdd(&cp[d], acc[d]);
}

// d_inv[h,n] = 1 / (qf[h,n,:] . ksum[h,:])    (warp per row)
__global__ void dinv_kernel(const float* __restrict__ qf, const float* __restrict__ ksum,
                            float* __restrict__ dinv) {
    int w = (blockIdx.x * blockDim.x + threadIdx.x) >> 5;
    int lane = threadIdx.x & 31;
    if (w >= HEADS * NTOK) return;
    int h = w >> 12;
    const float* qr = qf + (size_t)w * MFEAT;
    const float* ks = ksum + h * MFEAT;
    float s = 0.0f;
    #pragma unroll
    for (int m = lane; m < MFEAT; m += 32) s += qr[m] * ks[m];
    #pragma unroll
    for (int off = 16; off; off >>= 1) s += __shfl_xor_sync(0xffffffffu, s, off);
    if (lane == 0) dinv[w] = 1.0f / s;
}

// o[n, h*64+d] = d_inv[h,n] * (qf[h,n,:] @ ctx[h,:,:])
__global__ void o_kernel(const float* __restrict__ qf, const float* __restrict__ ctx,
                         const float* __restrict__ dinv, float* __restrict__ o) {
    int h = blockIdx.y;
    int n0 = blockIdx.x * 32;
    int t = threadIdx.x;
    __shared__ float sQ[32][64];
    __shared__ float sC[64][64];
    float acc[8];
    #pragma unroll
    for (int j = 0; j < 8; j++) acc[j] = 0.0f;
    int r = t >> 3, dl = t & 7;
    for (int mc = 0; mc < MFEAT; mc += 64) {
        #pragma unroll
        for (int i = 0; i < 8; i++) {
            int idx = t + i * 256, rr = idx >> 6, cc = idx & 63;
            sQ[rr][cc] = qf[((size_t)((h << 12) + n0 + rr)) * MFEAT + mc + cc];
        }
        #pragma unroll
        for (int i = 0; i < 16; i++) {
            int idx = t + i * 256, rr = idx >> 6, cc = idx & 63;
            sC[rr][cc] = ctx[((size_t)h * MFEAT + mc + rr) * DH + cc];
        }
        __syncthreads();
        #pragma unroll
        for (int m = 0; m < 64; m++) {
            float qv = sQ[r][m];
            #pragma unroll
            for (int j = 0; j < 8; j++) acc[j] += qv * sC[m][dl + 8 * j];
        }
        __syncthreads();
    }
    float di = dinv[(h << 12) + n0 + r];
    #pragma unroll
    for (int j = 0; j < 8; j++)
        o[(size_t)(n0 + r) * DIM + h * DH + dl + 8 * j] = acc[j] * di;
}

// ---------------- host ------------------------------------------------------
static void launch_sgemm(int epi, const float* A, const float* B, const float* bias,
                         const float* res, float* C, int M, int N, int K) {
    dim3 grid((N + 127) / 128, (M + 127) / 128);
    switch (epi) {
        case 0: sgemm_kernel<0><<<grid, 256>>>(A, B, bias, res, C, M, N, K); break;
        case 1: sgemm_kernel<1><<<grid, 256>>>(A, B, bias, res, C, M, N, K); break;
        case 2: sgemm_kernel<2><<<grid, 256>>>(A, B, bias, res, C, M, N, K); break;
        case 3: sgemm_kernel<3><<<grid, 256>>>(A, B, bias, res, C, M, N, K); break;
    }
}

extern "C" void kernel_launch(void* const* d_in, const int* in_sizes, int n_in,
                              void* d_out, int out_size) {
    const float* methy  = (const float*)d_in[0];
    const int*   chromo = (const int*)  d_in[1];
    const int*   pos    = (const int*)  d_in[2];
    const float* mtab   = (const float*)d_in[3];
    const float* ctab   = (const float*)d_in[4];
    const float* ptab   = (const float*)d_in[5];
    const float* ln1g   = (const float*)d_in[6];
    const float* ln1b   = (const float*)d_in[7];
    const float* ln2g   = (const float*)d_in[8];
    const float* ln2b   = (const float*)d_in[9];
    const float* Wq     = (const float*)d_in[10];
    const float* Wk     = (const float*)d_in[11];
    const float* Wv     = (const float*)d_in[12];
    const float* Wo     = (const float*)d_in[13];
    const float* bo     = (const float*)d_in[14];
    const float* W1     = (const float*)d_in[15];
    const float* b1     = (const float*)d_in[16];
    const float* W2     = (const float*)d_in[17];
    const float* b2     = (const float*)d_in[18];
    const float* proj   = (const float*)d_in[19];
    const float* nfg    = (const float*)d_in[20];
    const float* nfb    = (const float*)d_in[21];
    const float* Wout   = (const float*)d_in[22];
    const float* bout   = (const float*)d_in[23];
    float* out = (float*)d_out;

    float *px, *ph, *pq, *pk, *pv, *po, *pff, *pqf, *pkf, *pdiag, *pksum, *pctx, *pdinv;
    unsigned* phmax; int* pbidx;
    cudaGetSymbolAddress((void**)&px,    g_x);
    cudaGetSymbolAddress((void**)&ph,    g_h);
    cudaGetSymbolAddress((void**)&pq,    g_q);
    cudaGetSymbolAddress((void**)&pk,    g_k);
    cudaGetSymbolAddress((void**)&pv,    g_v);
    cudaGetSymbolAddress((void**)&po,    g_o);
    cudaGetSymbolAddress((void**)&pff,   g_ff);
    cudaGetSymbolAddress((void**)&pqf,   g_qf);
    cudaGetSymbolAddress((void**)&pkf,   g_kf);
    cudaGetSymbolAddress((void**)&pdiag, g_diag);
    cudaGetSymbolAddress((void**)&pksum, g_ksum);
    cudaGetSymbolAddress((void**)&pctx,  g_ctx);
    cudaGetSymbolAddress((void**)&pdinv, g_dinv);
    cudaGetSymbolAddress((void**)&phmax, g_hmax);
    cudaGetSymbolAddress((void**)&pbidx, g_bidx);

    bucket_kernel<<<16, 256>>>(methy, pbidx);
    embed_kernel<<<NTOK, 256>>>(pbidx, pos, chromo, mtab, ptab, ctab, px);

    for (int l = 0; l < DEPTH; l++) {
        const float* prl = proj + (size_t)l * MFEAT * DH;
        ln_kernel<<<NTOK, 256>>>(px, ln1g + l * DIM, ln1b + l * DIM, ph);
        launch_sgemm(0, ph, Wq + (size_t)l * DIM * DIM, nullptr, nullptr, pq, NTOK, DIM, DIM);
        launch_sgemm(0, ph, Wk + (size_t)l * DIM * DIM, nullptr, nullptr, pk, NTOK, DIM, DIM);
        launch_sgemm(0, ph, Wv + (size_t)l * DIM * DIM, nullptr, nullptr, pv, NTOK, DIM, DIM);

        cudaMemsetAsync(phmax, 0, HEADS * sizeof(unsigned));
        cudaMemsetAsync(pksum, 0, HEADS * MFEAT * sizeof(float));
        cudaMemsetAsync(pctx,  0, HEADS * MFEAT * DH * sizeof(float));

        favor_q_kernel<<<dim3(NTOK, HEADS), 256>>>(pq, prl, pqf);
        favor_k1_kernel<<<dim3(NTOK, HEADS), 256>>>(pk, prl, pkf, pdiag, phmax);
        favor_k2_kernel<<<HEADS * NTOK, 256>>>(pkf, pdiag, phmax, methy);
        ksum_kernel<<<dim3(16, HEADS), 256>>>(pkf, pksum);
        ctx_kernel<<<dim3(32, HEADS), 256>>>(pkf, pv, pctx);
        dinv_kernel<<<HEADS * NTOK / 8, 256>>>(pqf, pksum, pdinv);
        o_kernel<<<dim3(NTOK / 32, HEADS), 256>>>(pqf, pctx, pdinv, po);

        launch_sgemm(3, po, Wo + (size_t)l * DIM * DIM, bo + l * DIM, px, px, NTOK, DIM, DIM);
        ln_kernel<<<NTOK, 256>>>(px, ln2g + l * DIM, ln2b + l * DIM, ph);
        launch_sgemm(2, ph, W1 + (size_t)l * DIM * FFD, b1 + l * FFD, nullptr, pff, NTOK, FFD, DIM);
        launch_sgemm(3, pff, W2 + (size_t)l * FFD * DIM, b2 + l * DIM, px, px, NTOK, DIM, FFD);
    }

    ln_kernel<<<NTOK, 256>>>(px, nfg, nfb, ph);
    launch_sgemm(1, ph, Wout, bout, nullptr, out, NTOK, NOUT, DIM);
}

// round 5
// speedup vs baseline: 4.3337x; 4.3337x over previous
#include <cuda_runtime.h>
#include <math.h>
#include <stdint.h>

#define NTOK  4096
#define DIM   768
#define DEPTH 6
#define HEADS 12
#define DH    64
#define FFD   3072
#define MFEAT 256
#define NOUT  102

// ---------------- scratch (static device globals; no allocations) ----------
__device__ float g_x  [NTOK*DIM];
__device__ float g_h  [NTOK*DIM];
__device__ float g_q  [NTOK*DIM];
__device__ float g_k  [NTOK*DIM];
__device__ float g_v  [NTOK*DIM];
__device__ float g_o  [NTOK*DIM];
__device__ float g_ff [NTOK*FFD];
__device__ float g_qf [HEADS*NTOK*MFEAT];
__device__ float g_kf [HEADS*NTOK*MFEAT];
__device__ unsigned g_hmax[HEADS];
__device__ float g_ksum[HEADS*MFEAT];
__device__ float g_ctx [HEADS*MFEAT*DH];
__device__ float g_dinv[HEADS*NTOK];
__device__ int   g_bidx[NTOK];
__device__ float g_projT[DH*MFEAT];

// ---------------- helpers ---------------------------------------------------
__device__ __forceinline__ unsigned f2o(float f) {
    unsigned u = __float_as_uint(f);
    return (u & 0x80000000u) ? ~u : (u | 0x80000000u);
}
__device__ __forceinline__ float o2f(unsigned u) {
    return __uint_as_float((u & 0x80000000u) ? (u & 0x7fffffffu) : ~u);
}
__device__ __forceinline__ float gelu_tanh(float x) {
    float x3 = x * x * x;
    return 0.5f * x * (1.0f + tanhf(0.7978845608028654f * (x + 0.044715f * x3)));
}

// ---------------- embedding -------------------------------------------------
__global__ void bucket_kernel(const float* __restrict__ methy, int* __restrict__ idx) {
    int n = blockIdx.x * 256 + threadIdx.x;
    if (n >= NTOK) return;
    float v = methy[n];
    int c = 0;
    c += (v > -2.0f);
    c += (v > -1.0f);
    #pragma unroll
    for (int k = 0; k < 100; k++) c += (v > (float)k * 0.01f);
    idx[n] = c;
}

__global__ void embed_kernel(const int* __restrict__ idx, const int* __restrict__ pos,
                             const int* __restrict__ chromo,
                             const float* __restrict__ mtab, const float* __restrict__ ptab,
                             const float* __restrict__ ctab, float* __restrict__ x) {
    int n = blockIdx.x;
    int t = threadIdx.x;
    int mi = idx[n], pi = pos[n], ci = chromo[n];
    #pragma unroll
    for (int i = 0; i < 3; i++) {
        int d = t + i * 256;
        x[(size_t)n * DIM + d] = mtab[(size_t)mi * DIM + d]
                               + ptab[(size_t)pi * DIM + d]
                               + ctab[(size_t)ci * DIM + d];
    }
}

// ---------------- layernorm (one block per row, 768 = 3*256) ----------------
__global__ void ln_kernel(const float* __restrict__ x, const float* __restrict__ g,
                          const float* __restrict__ b, float* __restrict__ out) {
    __shared__ float red[256];
    int n = blockIdx.x, t = threadIdx.x;
    const float* xr = x + (size_t)n * DIM;
    float v0 = xr[t], v1 = xr[t + 256], v2 = xr[t + 512];
    red[t] = v0 + v1 + v2;
    __syncthreads();
    for (int s = 128; s; s >>= 1) { if (t < s) red[t] += red[t + s]; __syncthreads(); }
    float mu = red[0] * (1.0f / 768.0f);
    __syncthreads();
    float d0 = v0 - mu, d1 = v1 - mu, d2 = v2 - mu;
    red[t] = d0 * d0 + d1 * d1 + d2 * d2;
    __syncthreads();
    for (int s = 128; s; s >>= 1) { if (t < s) red[t] += red[t + s]; __syncthreads(); }
    float rstd = rsqrtf(red[0] * (1.0f / 768.0f) + 1e-5f);
    float* o = out + (size_t)n * DIM;
    o[t]       = d0 * rstd * g[t]       + b[t];
    o[t + 256] = d1 * rstd * g[t + 256] + b[t + 256];
    o[t + 512] = d2 * rstd * g[t + 512] + b[t + 512];
}

// ---------------- core tiled SGEMM (128x128x16, 8x8 micro via float4) -------
// EPI: 0 = none, 1 = +bias, 2 = gelu(+bias), 3 = +bias +res
template<int EPI, bool GUARD_N>
__device__ __forceinline__ void gemm_core(
    const float* __restrict__ A, int lda,
    const float* __restrict__ B, int ldb,
    const float* __restrict__ bias, const float* __restrict__ res,
    float* __restrict__ C, int ldc,
    int N, int K, int row0, int col0)
{
    __shared__ float As[16][132];   // padded: 132 floats = 528 B (16B aligned rows)
    __shared__ float Bs[16][128];

    int tid = threadIdx.x;
    int tx = tid & 15, ty = tid >> 4;
    // A tile loader: 128 rows x 16 k; thread -> rows (tid>>2) and 64+(tid>>2), k-chunk (tid&3)*4
    int arow = tid >> 2;
    int akc  = (tid & 3) * 4;
    // B tile loader: 16 rows x 128 cols; thread -> rows (tid>>5) and 8+(tid>>5), cols (tid&31)*4
    int brow = tid >> 5;
    int bcol = (tid & 31) * 4;

    float acc[8][8];
    #pragma unroll
    for (int i = 0; i < 8; i++)
        #pragma unroll
        for (int j = 0; j < 8; j++) acc[i][j] = 0.0f;

    float4 ra0, ra1, rb0, rb1;

    // prefetch k0 = 0
    {
        const float* Ap = A + (size_t)(row0 + arow) * lda + akc;
        ra0 = *(const float4*)Ap;
        ra1 = *(const float4*)(Ap + (size_t)64 * lda);
        if (GUARD_N) {
            const float* Bp0 = B + (size_t)brow * ldb + col0 + bcol;
            const float* Bp1 = B + (size_t)(brow + 8) * ldb + col0 + bcol;
            #pragma unroll
            for (int j = 0; j < 4; j++) {
                int c = col0 + bcol + j;
                ((float*)&rb0)[j] = (c < N) ? Bp0[j] : 0.0f;
                ((float*)&rb1)[j] = (c < N) ? Bp1[j] : 0.0f;
            }
        } else {
            rb0 = *(const float4*)(B + (size_t)brow * ldb + col0 + bcol);
            rb1 = *(const float4*)(B + (size_t)(brow + 8) * ldb + col0 + bcol);
        }
    }

    for (int k0 = 0; k0 < K; k0 += 16) {
        // stage to shared
        #pragma unroll
        for (int j = 0; j < 4; j++) {
            As[akc + j][arow]      = ((float*)&ra0)[j];
            As[akc + j][arow + 64] = ((float*)&ra1)[j];
        }
        *(float4*)&Bs[brow][bcol]     = rb0;
        *(float4*)&Bs[brow + 8][bcol] = rb1;
        __syncthreads();

        // prefetch next
        if (k0 + 16 < K) {
            const float* Ap = A + (size_t)(row0 + arow) * lda + k0 + 16 + akc;
            ra0 = *(const float4*)Ap;
            ra1 = *(const float4*)(Ap + (size_t)64 * lda);
            if (GUARD_N) {
                const float* Bp0 = B + (size_t)(k0 + 16 + brow) * ldb + col0 + bcol;
                const float* Bp1 = B + (size_t)(k0 + 24 + brow) * ldb + col0 + bcol;
                #pragma unroll
                for (int j = 0; j < 4; j++) {
                    int c = col0 + bcol + j;
                    ((float*)&rb0)[j] = (c < N) ? Bp0[j] : 0.0f;
                    ((float*)&rb1)[j] = (c < N) ? Bp1[j] : 0.0f;
                }
            } else {
                rb0 = *(const float4*)(B + (size_t)(k0 + 16 + brow) * ldb + col0 + bcol);
                rb1 = *(const float4*)(B + (size_t)(k0 + 24 + brow) * ldb + col0 + bcol);
            }
        }

        #pragma unroll
        for (int kk = 0; kk < 16; kk++) {
            const float4* As4 = (const float4*)&As[kk][0];
            const float4* Bs4 = (const float4*)&Bs[kk][0];
            float4 a0 = As4[ty], a1 = As4[ty + 16];
            float4 b0 = Bs4[tx], b1 = Bs4[tx + 16];
            float av[8] = {a0.x, a0.y, a0.z, a0.w, a1.x, a1.y, a1.z, a1.w};
            float bv[8] = {b0.x, b0.y, b0.z, b0.w, b1.x, b1.y, b1.z, b1.w};
            #pragma unroll
            for (int i = 0; i < 8; i++)
                #pragma unroll
                for (int j = 0; j < 8; j++) acc[i][j] += av[i] * bv[j];
        }
        __syncthreads();
    }

    // epilogue
    #pragma unroll
    for (int i = 0; i < 8; i++) {
        int r = row0 + (i < 4 ? ty * 4 + i : 64 + ty * 4 + (i - 4));
        #pragma unroll
        for (int half = 0; half < 2; half++) {
            int c0 = col0 + (half ? 64 + tx * 4 : tx * 4);
            if (GUARD_N) {
                #pragma unroll
                for (int j = 0; j < 4; j++) {
                    int c = c0 + j;
                    if (c < N) {
                        float v = acc[i][half * 4 + j];
                        if (EPI >= 1) v += bias[c];
                        if (EPI == 2) v = gelu_tanh(v);
                        if (EPI == 3) v += res[(size_t)r * ldc + c];
                        C[(size_t)r * ldc + c] = v;
                    }
                }
            } else {
                float4 v;
                v.x = acc[i][half * 4 + 0]; v.y = acc[i][half * 4 + 1];
                v.z = acc[i][half * 4 + 2]; v.w = acc[i][half * 4 + 3];
                if (EPI >= 1) {
                    float4 bb = *(const float4*)(bias + c0);
                    v.x += bb.x; v.y += bb.y; v.z += bb.z; v.w += bb.w;
                }
                if (EPI == 2) {
                    v.x = gelu_tanh(v.x); v.y = gelu_tanh(v.y);
                    v.z = gelu_tanh(v.z); v.w = gelu_tanh(v.w);
                }
                if (EPI == 3) {
                    float4 rr = *(const float4*)(res + (size_t)r * ldc + c0);
                    v.x += rr.x; v.y += rr.y; v.z += rr.z; v.w += rr.w;
                }
                *(float4*)(C + (size_t)r * ldc + c0) = v;
            }
        }
    }
}

template<int EPI>
__global__ __launch_bounds__(256, 2)
void sgemm_k(const float* __restrict__ A, int lda, const float* __restrict__ B, int ldb,
             const float* __restrict__ bias, const float* __restrict__ res,
             float* __restrict__ C, int ldc, int N, int K) {
    gemm_core<EPI, false>(A, lda, B, ldb, bias, res, C, ldc, N, K,
                          blockIdx.y * 128, blockIdx.x * 128);
}

__global__ __launch_bounds__(256, 2)
void sgemm_guard_k(const float* __restrict__ A, int lda, const float* __restrict__ B, int ldb,
                   const float* __restrict__ bias, float* __restrict__ C, int ldc,
                   int N, int K) {
    gemm_core<1, true>(A, lda, B, ldb, bias, nullptr, C, ldc, N, K,
                       blockIdx.y * 128, blockIdx.x * 128);
}

// fused QKV: blockIdx.z selects the weight / output
__global__ __launch_bounds__(256, 2)
void sgemm_qkv_k(const float* __restrict__ A,
                 const float* __restrict__ Bq, const float* __restrict__ Bk,
                 const float* __restrict__ Bv,
                 float* __restrict__ Cq, float* __restrict__ Ck, float* __restrict__ Cv) {
    int z = blockIdx.z;
    const float* B = (z == 0) ? Bq : (z == 1) ? Bk : Bv;
    float* C = (z == 0) ? Cq : (z == 1) ? Ck : Cv;
    gemm_core<0, false>(A, DIM, B, DIM, nullptr, nullptr, C, DIM, DIM, DIM,
                        blockIdx.y * 128, blockIdx.x * 128);
}

// FAVOR projection GEMM: xd[h][n][m] = x[n][h*64+d] @ (dnorm * proj^T)[d][m]
// z in [0,24): z<12 -> q path, else k path (h = z or z-12)
__global__ __launch_bounds__(256, 2)
void favor_xd_k(const float* __restrict__ q, const float* __restrict__ k,
                const float* __restrict__ projT,
                float* __restrict__ xq, float* __restrict__ xk) {
    int z = blockIdx.z;
    int h = (z < 12) ? z : z - 12;
    const float* A = ((z < 12) ? q : k) + h * DH;
    float* C = ((z < 12) ? xq : xk) + (size_t)h * NTOK * MFEAT;
    gemm_core<0, false>(A, DIM, projT, MFEAT, nullptr, nullptr, C, MFEAT, MFEAT, DH,
                        blockIdx.y * 128, blockIdx.x * 128);
}

// projT[d][m] = dnorm * proj[m][d]
__global__ void projT_kernel(const float* __restrict__ proj, float* __restrict__ projT) {
    int i = blockIdx.x * 256 + threadIdx.x;     // 16384
    int m = i >> 6, d = i & 63;
    projT[d * MFEAT + m] = 0.35355339059327373f * proj[i];
}

// ---------------- FAVOR+ post-processing -------------------------------------
// warp per (h,n) row: rowmax + diag + exp, in-place on xd
__global__ void q_post_kernel(const float* __restrict__ q, float* __restrict__ qf) {
    int gw = (blockIdx.x * 256 + threadIdx.x) >> 5;
    int lane = threadIdx.x & 31;
    int h = gw >> 12, n = gw & 4095;
    float* row = qf + (size_t)gw * MFEAT;
    float v[8];
    float mx = -3e38f;
    #pragma unroll
    for (int i = 0; i < 8; i++) { v[i] = row[lane + 32 * i]; mx = fmaxf(mx, v[i]); }
    #pragma unroll
    for (int off = 16; off; off >>= 1) mx = fmaxf(mx, __shfl_xor_sync(0xffffffffu, mx, off));
    const float* qr = q + (size_t)n * DIM + h * DH;
    float a = qr[lane], b = qr[lane + 32];
    float ss = a * a + b * b;
    #pragma unroll
    for (int off = 16; off; off >>= 1) ss += __shfl_xor_sync(0xffffffffu, ss, off);
    float diag = ss * 0.0625f;   // 0.5 * dnorm^2 = 1/16
    #pragma unroll
    for (int i = 0; i < 8; i++)
        row[lane + 32 * i] = 0.0625f * (expf(v[i] - diag - mx) + 1e-4f);
}

// per-head global max of raw xd_k
__global__ void k_max_kernel(const float* __restrict__ kf, unsigned* __restrict__ hmax) {
    __shared__ float red[256];
    int h = blockIdx.y, t = threadIdx.x;
    int n0 = blockIdx.x * 128;
    float m = -3e38f;
    for (int n = n0; n < n0 + 128; n++)
        m = fmaxf(m, kf[((size_t)((h << 12) + n)) * MFEAT + t]);
    red[t] = m;
    __syncthreads();
    for (int s = 128; s; s >>= 1) { if (t < s) red[t] = fmaxf(red[t], red[t + s]); __syncthreads(); }
    if (t == 0) atomicMax(hmax + h, f2o(red[0]));
}

__global__ void k_post_kernel(const float* __restrict__ k, float* __restrict__ kf,
                              const unsigned* __restrict__ hmax,
                              const float* __restrict__ methy) {
    int gw = (blockIdx.x * 256 + threadIdx.x) >> 5;
    int lane = threadIdx.x & 31;
    int h = gw >> 12, n = gw & 4095;
    float* row = kf + (size_t)gw * MFEAT;
    float mx = o2f(hmax[h]);
    const float* kr = k + (size_t)n * DIM + h * DH;
    float a = kr[lane], b = kr[lane + 32];
    float ss = a * a + b * b;
    #pragma unroll
    for (int off = 16; off; off >>= 1) ss += __shfl_xor_sync(0xffffffffu, ss, off);
    float diag = ss * 0.0625f;
    float msk = (methy[n] != 0.0f) ? 1.0f : 0.0f;
    #pragma unroll
    for (int i = 0; i < 8; i++) {
        float v = row[lane + 32 * i];
        row[lane + 32 * i] = msk * 0.0625f * (expf(v - diag - mx) + 1e-4f);
    }
}

// k_sum[h,m] += sum over 256-row n-chunk
__global__ void ksum_kernel(const float* __restrict__ kf, float* __restrict__ ksum) {
    int h = blockIdx.y, m = threadIdx.x;
    int n0 = blockIdx.x * 256;
    float s = 0.0f;
    for (int n = n0; n < n0 + 256; n++)
        s += kf[((size_t)((h << 12) + n)) * MFEAT + m];
    atomicAdd(&ksum[h * MFEAT + m], s);
}

// ctx[h,m,d] += sum_n kf[h,n,m]*v[n,h,d]
__global__ void ctx_kernel(const float* __restrict__ kf, const float* __restrict__ v,
                           float* __restrict__ ctx) {
    int h = blockIdx.y;
    int n0 = blockIdx.x * 128;
    int t = threadIdx.x;
    __shared__ float sv[4][64];
    float4 acc4[16];
    #pragma unroll
    for (int i = 0; i < 16; i++) acc4[i] = make_float4(0.f, 0.f, 0.f, 0.f);
    int rr = t >> 6, cc = t & 63;
    for (int n = n0; n < n0 + 128; n += 4) {
        sv[rr][cc] = v[(size_t)(n + rr) * DIM + h * DH + cc];
        __syncthreads();
        #pragma unroll
        for (int r = 0; r < 4; r++) {
            float kv = kf[((size_t)((h << 12) + n + r)) * MFEAT + t];
            const float4* vp = (const float4*)sv[r];
            #pragma unroll
            for (int d4 = 0; d4 < 16; d4++) {
                float4 vv = vp[d4];
                acc4[d4].x += kv * vv.x; acc4[d4].y += kv * vv.y;
                acc4[d4].z += kv * vv.z; acc4[d4].w += kv * vv.w;
            }
        }
        __syncthreads();
    }
    float* cp = ctx + ((size_t)h * MFEAT + t) * DH;
    #pragma unroll
    for (int d4 = 0; d4 < 16; d4++) {
        atomicAdd(&cp[d4 * 4 + 0], acc4[d4].x);
        atomicAdd(&cp[d4 * 4 + 1], acc4[d4].y);
        atomicAdd(&cp[d4 * 4 + 2], acc4[d4].z);
        atomicAdd(&cp[d4 * 4 + 3], acc4[d4].w);
    }
}

// d_inv[h,n] = 1 / (qf[h,n,:] . ksum[h,:])
__global__ void dinv_kernel(const float* __restrict__ qf, const float* __restrict__ ksum,
                            float* __restrict__ dinv) {
    int w = (blockIdx.x * blockDim.x + threadIdx.x) >> 5;
    int lane = threadIdx.x & 31;
    if (w >= HEADS * NTOK) return;
    int h = w >> 12;
    const float* qr = qf + (size_t)w * MFEAT;
    const float* ks = ksum + h * MFEAT;
    float s = 0.0f;
    #pragma unroll
    for (int m = lane; m < MFEAT; m += 32) s += qr[m] * ks[m];
    #pragma unroll
    for (int off = 16; off; off >>= 1) s += __shfl_xor_sync(0xffffffffu, s, off);
    if (lane == 0) dinv[w] = 1.0f / s;
}

// o[n, h*64 + d] = d_inv[h,n] * (qf[h,n,:] @ ctx[h,:,:])
__global__ void o_kernel(const float* __restrict__ qf, const float* __restrict__ ctx,
                         const float* __restrict__ dinv, float* __restrict__ o) {
    int h = blockIdx.y;
    int n0 = blockIdx.x * 32;
    int t = threadIdx.x;
    __shared__ float sQ[32][64];
    __shared__ float sC[64][64];
    int r = t >> 3, dl = t & 7;     // thread covers cols [dl*8, dl*8+8)
    float4 acc0 = make_float4(0.f, 0.f, 0.f, 0.f);
    float4 acc1 = make_float4(0.f, 0.f, 0.f, 0.f);
    for (int mc = 0; mc < MFEAT; mc += 64) {
        #pragma unroll
        for (int i = 0; i < 8; i++) {
            int idx = t + i * 256, rr = idx >> 6, cc = idx & 63;
            sQ[rr][cc] = qf[((size_t)((h << 12) + n0 + rr)) * MFEAT + mc + cc];
        }
        #pragma unroll
        for (int i = 0; i < 16; i++) {
            int idx = t + i * 256, rr = idx >> 6, cc = idx & 63;
            sC[rr][cc] = ctx[((size_t)h * MFEAT + mc + rr) * DH + cc];
        }
        __syncthreads();
        #pragma unroll
        for (int m = 0; m < 64; m++) {
            float qv = sQ[r][m];
            const float4* cp = (const float4*)sC[m];
            float4 c0 = cp[dl * 2], c1 = cp[dl * 2 + 1];
            acc0.x += qv * c0.x; acc0.y += qv * c0.y;
            acc0.z += qv * c0.z; acc0.w += qv * c0.w;
            acc1.x += qv * c1.x; acc1.y += qv * c1.y;
            acc1.z += qv * c1.z; acc1.w += qv * c1.w;
        }
        __syncthreads();
    }
    float di = dinv[(h << 12) + n0 + r];
    float* op = o + (size_t)(n0 + r) * DIM + h * DH + dl * 8;
    op[0] = acc0.x * di; op[1] = acc0.y * di; op[2] = acc0.z * di; op[3] = acc0.w * di;
    op[4] = acc1.x * di; op[5] = acc1.y * di; op[6] = acc1.z * di; op[7] = acc1.w * di;
}

// ---------------- host ------------------------------------------------------
extern "C" void kernel_launch(void* const* d_in, const int* in_sizes, int n_in,
                              void* d_out, int out_size) {
    const float* methy  = (const float*)d_in[0];
    const int*   chromo = (const int*)  d_in[1];
    const int*   pos    = (const int*)  d_in[2];
    const float* mtab   = (const float*)d_in[3];
    const float* ctab   = (const float*)d_in[4];
    const float* ptab   = (const float*)d_in[5];
    const float* ln1g   = (const float*)d_in[6];
    const float* ln1b   = (const float*)d_in[7];
    const float* ln2g   = (const float*)d_in[8];
    const float* ln2b   = (const float*)d_in[9];
    const float* Wq     = (const float*)d_in[10];
    const float* Wk     = (const float*)d_in[11];
    const float* Wv     = (const float*)d_in[12];
    const float* Wo     = (const float*)d_in[13];
    const float* bo     = (const float*)d_in[14];
    const float* W1     = (const float*)d_in[15];
    const float* b1     = (const float*)d_in[16];
    const float* W2     = (const float*)d_in[17];
    const float* b2     = (const float*)d_in[18];
    const float* proj   = (const float*)d_in[19];
    const float* nfg    = (const float*)d_in[20];
    const float* nfb    = (const float*)d_in[21];
    const float* Wout   = (const float*)d_in[22];
    const float* bout   = (const float*)d_in[23];
    float* out = (float*)d_out;

    float *px, *ph, *pq, *pk, *pv, *po, *pff, *pqf, *pkf, *pksum, *pctx, *pdinv, *pprojT;
    unsigned* phmax; int* pbidx;
    cudaGetSymbolAddress((void**)&px,     g_x);
    cudaGetSymbolAddress((void**)&ph,     g_h);
    cudaGetSymbolAddress((void**)&pq,     g_q);
    cudaGetSymbolAddress((void**)&pk,     g_k);
    cudaGetSymbolAddress((void**)&pv,     g_v);
    cudaGetSymbolAddress((void**)&po,     g_o);
    cudaGetSymbolAddress((void**)&pff,    g_ff);
    cudaGetSymbolAddress((void**)&pqf,    g_qf);
    cudaGetSymbolAddress((void**)&pkf,    g_kf);
    cudaGetSymbolAddress((void**)&pksum,  g_ksum);
    cudaGetSymbolAddress((void**)&pctx,   g_ctx);
    cudaGetSymbolAddress((void**)&pdinv,  g_dinv);
    cudaGetSymbolAddress((void**)&phmax,  g_hmax);
    cudaGetSymbolAddress((void**)&pbidx,  g_bidx);
    cudaGetSymbolAddress((void**)&pprojT, g_projT);

    bucket_kernel<<<16, 256>>>(methy, pbidx);
    embed_kernel<<<NTOK, 256>>>(pbidx, pos, chromo, mtab, ptab, ctab, px);

    for (int l = 0; l < DEPTH; l++) {
        const float* prl = proj + (size_t)l * MFEAT * DH;

        ln_kernel<<<NTOK, 256>>>(px, ln1g + l * DIM, ln1b + l * DIM, ph);
        sgemm_qkv_k<<<dim3(6, 32, 3), 256>>>(ph,
            Wq + (size_t)l * DIM * DIM, Wk + (size_t)l * DIM * DIM, Wv + (size_t)l * DIM * DIM,
            pq, pk, pv);

        cudaMemsetAsync(phmax, 0, HEADS * sizeof(unsigned));
        cudaMemsetAsync(pksum, 0, HEADS * MFEAT * sizeof(float));
        cudaMemsetAsync(pctx,  0, HEADS * MFEAT * DH * sizeof(float));

        projT_kernel<<<64, 256>>>(prl, pprojT);
        favor_xd_k<<<dim3(2, 32, 24), 256>>>(pq, pk, pprojT, pqf, pkf);
        q_post_kernel<<<HEADS * NTOK / 8, 256>>>(pq, pqf);
        k_max_kernel<<<dim3(32, HEADS), 256>>>(pkf, phmax);
        k_post_kernel<<<HEADS * NTOK / 8, 256>>>(pk, pkf, phmax, methy);
        ksum_kernel<<<dim3(16, HEADS), 256>>>(pkf, pksum);
        ctx_kernel<<<dim3(32, HEADS), 256>>>(pkf, pv, pctx);
        dinv_kernel<<<HEADS * NTOK / 8, 256>>>(pqf, pksum, pdinv);
        o_kernel<<<dim3(NTOK / 32, HEADS), 256>>>(pqf, pctx, pdinv, po);

        sgemm_k<3><<<dim3(6, 32), 256>>>(po, DIM, Wo + (size_t)l * DIM * DIM, DIM,
                                         bo + l * DIM, px, px, DIM, DIM, DIM);
        ln_kernel<<<NTOK, 256>>>(px, ln2g + l * DIM, ln2b + l * DIM, ph);
        sgemm_k<2><<<dim3(24, 32), 256>>>(ph, DIM, W1 + (size_t)l * DIM * FFD, FFD,
                                          b1 + l * FFD, nullptr, pff, FFD, FFD, DIM);
        sgemm_k<3><<<dim3(6, 32), 256>>>(pff, FFD, W2 + (size_t)l * FFD * DIM, DIM,
                                         b2 + l * DIM, px, px, DIM, DIM, FFD);
    }

    ln_kernel<<<NTOK, 256>>>(px, nfg, nfb, ph);
    sgemm_guard_k<<<dim3(1, 32), 256>>>(ph, DIM, Wout, NOUT, bout, out, NOUT, NOUT, DIM);
}